// round 2
// baseline (speedup 1.0000x reference)
#include <cuda_runtime.h>
#include <cuda_bf16.h>

#define THREADS 256          // one row (x sample) per thread
#define NB      67           // NUM_BASIS = GRID_SIZE + K = 64 + 3
#define TILE_FLOATS (THREADS * NB)     // 17152
#define TILE_VEC4   (TILE_FLOATS / 4)  // 4288 (exact)

// knot value U[k] for padded knot vector (71 knots):
// U[k] = clamp(k-3, 0, 64) * 0.03125 - 1   (exact fp32 binary values)
__device__ __forceinline__ float knot_at(int k) {
    int kk = k - 3;
    kk = kk < 0 ? 0 : (kk > 64 ? 64 : kk);
    return -1.0f + (float)kk * 0.03125f;
}

__global__ void __launch_bounds__(THREADS)
spline_basis_kernel(const float* __restrict__ x,
                    float* __restrict__ out,
                    int B)
{
    const int t = threadIdx.x;
    const int block0 = blockIdx.x * THREADS;      // first row of this block

    const long long outBase  = (long long)block0 * NB;
    const long long outTotal = (long long)B * NB;
    const long long remain   = outTotal - outBase; // floats in this block's region

    // ---- Phase 1: zero this block's output region directly (coalesced STG.128)
    // outBase*4 bytes is 16B-aligned: THREADS*NB*4 = 68608 is a multiple of 16.
    float4* ov = reinterpret_cast<float4*>(out + outBase);
    if (remain >= TILE_FLOATS) {
        #pragma unroll
        for (int i = t; i < TILE_VEC4; i += THREADS) {
            ov[i] = make_float4(0.f, 0.f, 0.f, 0.f);
        }
    } else {
        int nv4 = (int)(remain >> 2);              // full float4s
        for (int i = t; i < nv4; i += THREADS) {
            ov[i] = make_float4(0.f, 0.f, 0.f, 0.f);
        }
        // scalar tail (remain % 4 floats)
        for (int i = (int)(nv4 << 2) + t; i < (int)remain; i += THREADS) {
            out[outBase + i] = 0.f;
        }
    }

    // Order phase-1 zero stores before phase-2 value stores (within block).
    __syncthreads();

    // ---- Phase 2: each thread computes its row's 4 nonzero cubic basis values
    const int row = block0 + t;
    if (row < B) {
        const float xv = x[row];

        // cell index j in [0, 63]: grid spacing h = 2/64 = 0.03125
        float u = (xv + 1.0f) * 32.0f;
        int j = (int)floorf(u);
        j = j < 0 ? 0 : (j > 63 ? 63 : j);
        const int m = j + 3;   // knot span: U[m] <= x < U[m+1]

        // Cox-de Boor (NURBS A2.2), degree 3. N[0..3] = N_{j..j+3, 3}(x)
        float left1  = xv - knot_at(m);
        float right1 = knot_at(m + 1) - xv;
        float left2  = xv - knot_at(m - 1);
        float right2 = knot_at(m + 2) - xv;
        float left3  = xv - knot_at(m - 2);
        float right3 = knot_at(m + 3) - xv;

        float N0, N1, N2, N3;
        // d = 1
        {
            float temp = 1.0f / (right1 + left1);
            N0 = right1 * temp;
            N1 = left1 * temp;
        }
        // d = 2
        {
            float saved = 0.f;
            float temp = N0 / (right1 + left2);
            N0 = saved + right1 * temp;
            saved = left2 * temp;
            temp = N1 / (right2 + left1);
            N1 = saved + right2 * temp;
            N2 = left1 * temp;
        }
        // d = 3
        {
            float saved = 0.f;
            float temp = N0 / (right1 + left3);
            N0 = saved + right1 * temp;
            saved = left3 * temp;
            temp = N1 / (right2 + left2);
            N1 = saved + right2 * temp;
            saved = left2 * temp;
            temp = N2 / (right3 + left1);
            N2 = saved + right3 * temp;
            N3 = left1 * temp;
        }

        // scatter the 4 nonzero values at columns j..j+3 of this row.
        // These merge into the L2-resident lines zeroed in phase 1.
        float* rp = out + (long long)row * NB + j;
        rp[0] = N0;
        rp[1] = N1;
        rp[2] = N2;
        rp[3] = N3;
    }
}

extern "C" void kernel_launch(void* const* d_in, const int* in_sizes, int n_in,
                              void* d_out, int out_size)
{
    const float* x = (const float*)d_in[0];
    float* out = (float*)d_out;
    const int B = in_sizes[0];
    const int grid = (B + THREADS - 1) / THREADS;
    spline_basis_kernel<<<grid, THREADS>>>(x, out, B);
}

// round 3
// speedup vs baseline: 1.1101x; 1.1101x over previous
#include <cuda_runtime.h>
#include <cuda_bf16.h>

#define THREADS 256          // threads per block
#define ROWS    128          // rows (x samples) per block
#define NB      67           // NUM_BASIS = GRID_SIZE + K = 64 + 3
#define TILE_FLOATS (ROWS * NB)       // 8576
#define TILE_VEC4   (TILE_FLOATS/4)   // 2144 (exact)

// knot value U[k] for padded knot vector (71 knots):
// U[k] = clamp(k-3, 0, 64) * 0.03125 - 1   (exact fp32 binary values)
__device__ __forceinline__ float knot_at(int k) {
    int kk = k - 3;
    kk = kk < 0 ? 0 : (kk > 64 ? 64 : kk);
    return -1.0f + (float)kk * 0.03125f;
}

__global__ void __launch_bounds__(THREADS, 6)
spline_basis_kernel(const float* __restrict__ x,
                    float* __restrict__ out,
                    int B)
{
    __shared__ __align__(16) float tile[TILE_FLOATS];

    const int t = threadIdx.x;
    const int block0 = blockIdx.x * ROWS;

    // ---- Phase 1: zero the tile (vectorized STS.128, split over 256 threads)
    float4* tv = reinterpret_cast<float4*>(tile);
    #pragma unroll
    for (int i = t; i < TILE_VEC4; i += THREADS) {
        tv[i] = make_float4(0.f, 0.f, 0.f, 0.f);
    }
    __syncthreads();

    // ---- Phase 2: threads 0..127 each compute one row's 4 nonzero values
    if (t < ROWS) {
        const int row = block0 + t;
        if (row < B) {
            const float xv = x[row];

            // cell index j in [0, 63]: grid spacing h = 2/64 = 0.03125
            float u = (xv + 1.0f) * 32.0f;
            int j = (int)floorf(u);
            j = j < 0 ? 0 : (j > 63 ? 63 : j);
            const int m = j + 3;   // knot span: U[m] <= x < U[m+1]

            // Cox-de Boor (NURBS A2.2), degree 3.
            float left1  = xv - knot_at(m);
            float right1 = knot_at(m + 1) - xv;
            float left2  = xv - knot_at(m - 1);
            float right2 = knot_at(m + 2) - xv;
            float left3  = xv - knot_at(m - 2);
            float right3 = knot_at(m + 3) - xv;

            float N0, N1, N2, N3;
            // d = 1
            {
                float temp = 1.0f / (right1 + left1);
                N0 = right1 * temp;
                N1 = left1 * temp;
            }
            // d = 2
            {
                float saved = 0.f;
                float temp = N0 / (right1 + left2);
                N0 = saved + right1 * temp;
                saved = left2 * temp;
                temp = N1 / (right2 + left1);
                N1 = saved + right2 * temp;
                N2 = left1 * temp;
            }
            // d = 3
            {
                float saved = 0.f;
                float temp = N0 / (right1 + left3);
                N0 = saved + right1 * temp;
                saved = left3 * temp;
                temp = N1 / (right2 + left2);
                N1 = saved + right2 * temp;
                saved = left2 * temp;
                temp = N2 / (right3 + left1);
                N2 = saved + right3 * temp;
                N3 = left1 * temp;
            }

            const int base = t * NB + j;
            tile[base + 0] = N0;
            tile[base + 1] = N1;
            tile[base + 2] = N2;
            tile[base + 3] = N3;
        }
    }
    __syncthreads();

    // ---- Phase 3: coalesced copy-out (LDS.128 + STG.128), 256 threads
    const long long outBase  = (long long)block0 * NB;
    const long long outTotal = (long long)B * NB;
    const long long remain   = outTotal - outBase;

    if (remain >= TILE_FLOATS) {
        // full tile (outBase*4 bytes is 16B-aligned: 128*67*4 % 16 == 0)
        float4* ov = reinterpret_cast<float4*>(out + outBase);
        #pragma unroll
        for (int i = t; i < TILE_VEC4; i += THREADS) {
            ov[i] = tv[i];
        }
    } else {
        // tail block: scalar bounded copy
        for (int i = t; i < (int)remain; i += THREADS) {
            out[outBase + i] = tile[i];
        }
    }
}

extern "C" void kernel_launch(void* const* d_in, const int* in_sizes, int n_in,
                              void* d_out, int out_size)
{
    const float* x = (const float*)d_in[0];
    float* out = (float*)d_out;
    const int B = in_sizes[0];
    const int grid = (B + ROWS - 1) / ROWS;
    spline_basis_kernel<<<grid, THREADS>>>(x, out, B);
}

// round 4
// speedup vs baseline: 1.1730x; 1.0566x over previous
#include <cuda_runtime.h>
#include <cuda_bf16.h>
#include <cstdint>

#define THREADS 256          // threads per block
#define ROWS    128          // rows (x samples) per block
#define NB      67           // NUM_BASIS = GRID_SIZE + K = 64 + 3
#define TILE_FLOATS (ROWS * NB)       // 8576
#define TILE_BYTES  (TILE_FLOATS * 4) // 34304 (multiple of 16)
#define TILE_VEC4   (TILE_FLOATS/4)   // 2144 (exact)

// knot value U[k] for padded knot vector (71 knots):
// U[k] = clamp(k-3, 0, 64) * 0.03125 - 1   (exact fp32 binary values)
__device__ __forceinline__ float knot_at(int k) {
    int kk = k - 3;
    kk = kk < 0 ? 0 : (kk > 64 ? 64 : kk);
    return -1.0f + (float)kk * 0.03125f;
}

__device__ __forceinline__ uint32_t smem_u32(const void* p) {
    uint32_t a;
    asm("{ .reg .u64 t; cvta.to.shared.u64 t, %1; cvt.u32.u64 %0, t; }"
        : "=r"(a) : "l"(p));
    return a;
}

__global__ void __launch_bounds__(THREADS, 6)
spline_basis_kernel(const float* __restrict__ x,
                    float* __restrict__ out,
                    int B)
{
    __shared__ __align__(16) float tile[TILE_FLOATS];

    const int t = threadIdx.x;
    const int block0 = blockIdx.x * ROWS;

    // ---- Phase 1: zero the tile (vectorized STS.128, 256 threads)
    float4* tv = reinterpret_cast<float4*>(tile);
    #pragma unroll
    for (int i = t; i < TILE_VEC4; i += THREADS) {
        tv[i] = make_float4(0.f, 0.f, 0.f, 0.f);
    }
    __syncthreads();

    // ---- Phase 2: threads 0..127 each compute one row's 4 nonzero values
    if (t < ROWS) {
        const int row = block0 + t;
        if (row < B) {
            const float xv = x[row];

            // cell index j in [0, 63]: grid spacing h = 2/64 = 0.03125
            float u = (xv + 1.0f) * 32.0f;
            int j = (int)floorf(u);
            j = j < 0 ? 0 : (j > 63 ? 63 : j);
            const int m = j + 3;   // knot span: U[m] <= x < U[m+1]

            // Cox-de Boor (NURBS A2.2), degree 3.
            float left1  = xv - knot_at(m);
            float right1 = knot_at(m + 1) - xv;
            float left2  = xv - knot_at(m - 1);
            float right2 = knot_at(m + 2) - xv;
            float left3  = xv - knot_at(m - 2);
            float right3 = knot_at(m + 3) - xv;

            float N0, N1, N2, N3;
            // d = 1
            {
                float temp = 1.0f / (right1 + left1);
                N0 = right1 * temp;
                N1 = left1 * temp;
            }
            // d = 2
            {
                float saved = 0.f;
                float temp = N0 / (right1 + left2);
                N0 = saved + right1 * temp;
                saved = left2 * temp;
                temp = N1 / (right2 + left1);
                N1 = saved + right2 * temp;
                N2 = left1 * temp;
            }
            // d = 3
            {
                float saved = 0.f;
                float temp = N0 / (right1 + left3);
                N0 = saved + right1 * temp;
                saved = left3 * temp;
                temp = N1 / (right2 + left2);
                N1 = saved + right2 * temp;
                saved = left2 * temp;
                temp = N2 / (right3 + left1);
                N2 = saved + right3 * temp;
                N3 = left1 * temp;
            }

            const int base = t * NB + j;
            tile[base + 0] = N0;
            tile[base + 1] = N1;
            tile[base + 2] = N2;
            tile[base + 3] = N3;
        }
    }
    __syncthreads();

    // ---- Phase 3: bulk async store SMEM -> GMEM (TMA engine)
    const long long outBase  = (long long)block0 * NB;
    const long long outTotal = (long long)B * NB;
    const long long remain   = outTotal - outBase;

    if (remain >= TILE_FLOATS) {
        if (t == 0) {
            // order generic-proxy smem writes before async-proxy read
            asm volatile("fence.proxy.async.shared::cta;" ::: "memory");
            uint32_t s = smem_u32(tile);
            asm volatile(
                "cp.async.bulk.global.shared::cta.bulk_group [%0], [%1], %2;"
                :: "l"(out + outBase), "r"(s), "n"(TILE_BYTES) : "memory");
            asm volatile("cp.async.bulk.commit_group;" ::: "memory");
            asm volatile("cp.async.bulk.wait_group 0;" ::: "memory");
        }
    } else {
        // tail block (not hit for B=2,000,000): scalar bounded copy
        for (int i = t; i < (int)remain; i += THREADS) {
            out[outBase + i] = tile[i];
        }
    }
}

extern "C" void kernel_launch(void* const* d_in, const int* in_sizes, int n_in,
                              void* d_out, int out_size)
{
    const float* x = (const float*)d_in[0];
    float* out = (float*)d_out;
    const int B = in_sizes[0];
    const int grid = (B + ROWS - 1) / ROWS;
    spline_basis_kernel<<<grid, THREADS>>>(x, out, B);
}